// round 12
// baseline (speedup 1.0000x reference)
#include <cuda_runtime.h>
#include <cuda_fp16.h>
#include <cstdint>

#define Bsz 8
#define Cch 64
#define Hh  128
#define Wwi 128
#define Och 64
#define HW  (Hh*Wwi)

#define THREADS 256
#define NBLK    (Bsz*64)        // 512 CTAs, 2 rows each
#define NSUPER  4               // super-groups of 16 channels
#define NPH     9               // phases per super-group
#define NSTEPS  (NSUPER*NPH)    // 36

// smem (4B units): two chunk buffers [x: 16ch x (4*132), stride 532 | gc: 16 x (2x128), stride 260]
// + gs half2 packs [2 tiles][9][128]
#define XSTR    532             // 2*532 = 1064 ≡ 8 (mod 32): qp-groups conflict-free
#define XGC_OFF (16*XSTR)       // 8512
#define GCSTR   260             // 2*260 = 520 ≡ 8 (mod 32)
#define BUF_FL  (XGC_OFF + 16*GCSTR)   // 12672
#define GS_OFF  (2*BUF_FL)             // 25344
#define SMEM_U  (GS_OFF + 2*9*128)     // 27648 -> 110592 B

#define X_ELEMS  (16*4*132)            // 8448
#define GC_ELEMS (16*2*128)            // 4096

// B fragments: [step=36][j=4][lane=32] x uint4, lane innermost (coalesced)
__device__ uint4 d_bfrag[NSTEPS*4*32];

// ---------------- helpers ----------------
__device__ __forceinline__ uint32_t smem_u32(const void* p) {
    uint32_t a;
    asm("{ .reg .u64 t; cvta.to.shared.u64 t, %1; cvt.u32.u64 %0, t; }"
        : "=r"(a) : "l"(p));
    return a;
}
__device__ __forceinline__ void cp4(uint32_t dst, const void* src, int nbytes) {
    asm volatile("cp.async.ca.shared.global [%0], [%1], 4, %2;"
                 :: "r"(dst), "l"(src), "r"(nbytes));
}
__device__ __forceinline__ void cp_commit() { asm volatile("cp.async.commit_group;"); }
__device__ __forceinline__ void cp_wait1()  { asm volatile("cp.async.wait_group 1;" ::: "memory"); }
__device__ __forceinline__ void cp_wait0()  { asm volatile("cp.async.wait_group 0;" ::: "memory"); }
__device__ __forceinline__ uint32_t packh2(float lo, float hi) {
    __half2 h = __floats2half2_rn(lo, hi);
    return *reinterpret_cast<uint32_t*>(&h);
}
__device__ __forceinline__ uint32_t hadd2(uint32_t a, uint32_t b) {
    uint32_t r; asm("add.f16x2 %0, %1, %2;" : "=r"(r) : "r"(a), "r"(b)); return r;
}
__device__ __forceinline__ uint32_t tanh_h2(uint32_t a) {
    uint32_t r; asm("tanh.approx.f16x2 %0, %1;" : "=r"(r) : "r"(a)); return r;
}
__device__ __forceinline__ uint32_t hfma2(uint32_t a, uint32_t b, uint32_t c) {
    uint32_t r; asm("fma.rn.f16x2 %0, %1, %2, %3;" : "=r"(r) : "r"(a), "r"(b), "r"(c)); return r;
}
__device__ __forceinline__ void hmma(float& c0, float& c1, float& c2, float& c3,
                                     uint32_t a0, uint32_t a1, uint32_t a2, uint32_t a3,
                                     uint32_t b0, uint32_t b1) {
    asm("mma.sync.aligned.m16n8k16.row.col.f32.f16.f16.f32 "
        "{%0,%1,%2,%3}, {%4,%5,%6,%7}, {%8,%9}, {%0,%1,%2,%3};"
        : "+f"(c0), "+f"(c1), "+f"(c2), "+f"(c3)
        : "r"(a0), "r"(a1), "r"(a2), "r"(a3), "r"(b0), "r"(b1));
}

// ---------------- B fragment prep: step (g,p), slot s -> w[o][g*16+s][p] ----
__global__ void prep_bfrag(const float* __restrict__ w) {
    int i = blockIdx.x * blockDim.x + threadIdx.x;   // [step][j][lane]
    if (i < NSTEPS*4*32) {
        int lane = i & 31;
        int j    = (i >> 5) & 3;
        int step = i >> 7;
        int g    = step / NPH;
        int p    = step - g*NPH;
        int kb   = (lane & 3) * 2;
        uint32_t v[4];
        #pragma unroll
        for (int t = 0; t < 2; ++t) {
            int nt = 2*j + t;
            int o  = nt*8 + (lane >> 2);
            float f[4];
            #pragma unroll
            for (int q = 0; q < 4; ++q) {
                int s = kb + (q >> 1)*8 + (q & 1);
                int c = g*16 + s;
                f[q] = w[(o*Cch + c)*9 + p];
            }
            v[2*t]   = packh2(f[0], f[1]);
            v[2*t+1] = packh2(f[2], f[3]);
        }
        uint4 r; r.x = v[0]; r.y = v[1]; r.z = v[2]; r.w = v[3];
        d_bfrag[i] = r;
    }
}

// ---------------- main kernel ----------------
extern __shared__ float sm[];

__global__ void __launch_bounds__(THREADS, 2)
paka_hmma(const float* __restrict__ x,
          const float* __restrict__ gc,
          const float* __restrict__ gsp,
          float* __restrict__ out)
{
    const int tid  = threadIdx.x;
    const int lane = tid & 31;
    const int wid  = tid >> 5;
    const int t    = blockIdx.x;
    const int b    = t >> 6;
    const int h0   = (t & 63) << 1;      // rows h0, h0+1

    const uint32_t sbase = smem_u32(sm);

    // ---- gs half2 packs into smem (once) ----
    {
        uint32_t* gsm = (uint32_t*)(sm + GS_OFF);
        #pragma unroll
        for (int it = 0; it < 9; ++it) {
            int idx = tid + it*THREADS;
            if (idx < 2*9*128) {
                int tile = idx / 1152;
                int rem  = idx - tile*1152;
                int p    = rem >> 7;
                int col  = rem & 127;
                float v = __ldg(gsp + (((size_t)b*9 + p)*Hh + h0 + tile)*Wwi + col);
                gsm[idx] = packh2(v, v);
            }
        }
    }

    // ---- staging ----
    const float* xB  = x  + (size_t)b*Cch*HW;
    const float* gcB = gc + (size_t)b*Cch*HW + (size_t)h0*Wwi;
    auto stage_chunk = [&](int cg) {
        const uint32_t dst = sbase + (cg & 1)*BUF_FL*4;
        const float* xc = xB + (size_t)cg*16*HW;
        #pragma unroll
        for (int it = 0; it < 33; ++it) {
            int idx = tid + it*THREADS;
            if (idx < X_ELEMS) {
                int y   = idx >> 4;                       // idx/16 (0..527 after /33 step)
                int cl  = (int)(((unsigned)y * 993u) >> 15);       // idx/528
                int rem = idx - cl*528;
                int r4  = (int)((((unsigned)rem >> 2) * 993u) >> 15);  // rem/132
                int col = rem - r4*132;
                int gh  = h0 - 1 + r4;
                int gw  = col - 1;
                bool inb = ((unsigned)gh < Hh) & ((unsigned)gw < Wwi);
                const float* src = inb ? (xc + (size_t)cl*HW + gh*Wwi + gw) : xB;
                cp4(dst + (uint32_t)(cl*XSTR + r4*132 + col)*4, src, inb ? 4 : 0);
            }
        }
        const float* gcc = gcB + (size_t)cg*16*HW;
        #pragma unroll
        for (int it = 0; it < 16; ++it) {
            int idx = tid + it*THREADS;
            int cl  = idx >> 8;
            int rem = idx & 255;
            int row = rem >> 7;
            int col = rem & 127;
            cp4(dst + (uint32_t)(XGC_OFF + cl*GCSTR + row*128 + col)*4,
                gcc + (size_t)cl*HW + row*Wwi + col, 4);
        }
    };
    stage_chunk(0);
    cp_commit();

    const int r0 = wid*16 + (lane >> 2);
    const int r1 = r0 + 8;
    const int qp = (lane & 3)*2;

    float acc0[32], acc1[32];
    #pragma unroll
    for (int i = 0; i < 32; ++i) { acc0[i] = 0.f; acc1[i] = 0.f; }

    const uint32_t* gsm = (const uint32_t*)(sm + GS_OFF);

    for (int g = 0; g < NSUPER; ++g) {
        if (g + 1 < NSUPER) { stage_chunk(g + 1); cp_commit(); cp_wait1(); }
        else                { cp_wait0(); }
        __syncthreads();

        const float* bs = sm + (g & 1)*BUF_FL;
        // per-thread channel base pointers (channels qp, qp+1, qp+8, qp+9); tile1 = +132
        const float* p00 = bs + (qp    )*XSTR + r0;
        const float* p01 = bs + (qp    )*XSTR + r1;
        const float* p10 = bs + (qp + 1)*XSTR + r0;
        const float* p11 = bs + (qp + 1)*XSTR + r1;
        const float* p20 = bs + (qp + 8)*XSTR + r0;
        const float* p21 = bs + (qp + 8)*XSTR + r1;
        const float* p30 = bs + (qp + 9)*XSTR + r0;
        const float* p31 = bs + (qp + 9)*XSTR + r1;

        // gc half2 packs: [tile][pair(lo,hi)=ch qp/qp+1 or qp+8/qp+9][row r0/r1]
        const float* gp = bs + XGC_OFF;
        const uint32_t c0_0 = packh2(gp[(qp  )*GCSTR + r0],       gp[(qp+1)*GCSTR + r0]);
        const uint32_t c0_1 = packh2(gp[(qp  )*GCSTR + r1],       gp[(qp+1)*GCSTR + r1]);
        const uint32_t c0_2 = packh2(gp[(qp+8)*GCSTR + r0],       gp[(qp+9)*GCSTR + r0]);
        const uint32_t c0_3 = packh2(gp[(qp+8)*GCSTR + r1],       gp[(qp+9)*GCSTR + r1]);
        const uint32_t c1_0 = packh2(gp[(qp  )*GCSTR + 128 + r0], gp[(qp+1)*GCSTR + 128 + r0]);
        const uint32_t c1_1 = packh2(gp[(qp  )*GCSTR + 128 + r1], gp[(qp+1)*GCSTR + 128 + r1]);
        const uint32_t c1_2 = packh2(gp[(qp+8)*GCSTR + 128 + r0], gp[(qp+9)*GCSTR + 128 + r0]);
        const uint32_t c1_3 = packh2(gp[(qp+8)*GCSTR + 128 + r1], gp[(qp+9)*GCSTR + 128 + r1]);

        #pragma unroll
        for (int p = 0; p < NPH; ++p) {
            const int di  = p / 3;
            const int dj  = p - 3*di;
            const int im0 = di*132 + dj;          // tile0; tile1 = +132
            const int im1 = im0 + 132;

            const uint4* bp = d_bfrag + (size_t)(g*NPH + p)*128 + lane;
            uint4 B0 = bp[0];
            uint4 B1 = bp[32];
            uint4 B2 = bp[64];
            uint4 B3 = bp[96];

            const uint32_t gs00 = gsm[p*128 + r0];
            const uint32_t gs01 = gsm[p*128 + r1];
            const uint32_t gs10 = gsm[1152 + p*128 + r0];
            const uint32_t gs11 = gsm[1152 + p*128 + r1];

            // ---- tile 0 ----
            {
                const uint32_t xp0 = packh2(p00[im0], p10[im0]);
                const uint32_t xp1 = packh2(p01[im0], p11[im0]);
                const uint32_t xp2 = packh2(p20[im0], p30[im0]);
                const uint32_t xp3 = packh2(p21[im0], p31[im0]);

                const uint32_t t0 = tanh_h2(hadd2(c0_0, gs00));
                const uint32_t t1 = tanh_h2(hadd2(c0_1, gs01));
                const uint32_t t2 = tanh_h2(hadd2(c0_2, gs00));
                const uint32_t t3 = tanh_h2(hadd2(c0_3, gs01));

                const uint32_t a0 = hfma2(xp0, t0, xp0);
                const uint32_t a1 = hfma2(xp1, t1, xp1);
                const uint32_t a2 = hfma2(xp2, t2, xp2);
                const uint32_t a3 = hfma2(xp3, t3, xp3);

                hmma(acc0[0],  acc0[1],  acc0[2],  acc0[3],  a0,a1,a2,a3, B0.x, B0.y);
                hmma(acc0[4],  acc0[5],  acc0[6],  acc0[7],  a0,a1,a2,a3, B0.z, B0.w);
                hmma(acc0[8],  acc0[9],  acc0[10], acc0[11], a0,a1,a2,a3, B1.x, B1.y);
                hmma(acc0[12], acc0[13], acc0[14], acc0[15], a0,a1,a2,a3, B1.z, B1.w);
                hmma(acc0[16], acc0[17], acc0[18], acc0[19], a0,a1,a2,a3, B2.x, B2.y);
                hmma(acc0[20], acc0[21], acc0[22], acc0[23], a0,a1,a2,a3, B2.z, B2.w);
                hmma(acc0[24], acc0[25], acc0[26], acc0[27], a0,a1,a2,a3, B3.x, B3.y);
                hmma(acc0[28], acc0[29], acc0[30], acc0[31], a0,a1,a2,a3, B3.z, B3.w);
            }
            // ---- tile 1 ----
            {
                const uint32_t xp0 = packh2(p00[im1], p10[im1]);
                const uint32_t xp1 = packh2(p01[im1], p11[im1]);
                const uint32_t xp2 = packh2(p20[im1], p30[im1]);
                const uint32_t xp3 = packh2(p21[im1], p31[im1]);

                const uint32_t t0 = tanh_h2(hadd2(c1_0, gs10));
                const uint32_t t1 = tanh_h2(hadd2(c1_1, gs11));
                const uint32_t t2 = tanh_h2(hadd2(c1_2, gs10));
                const uint32_t t3 = tanh_h2(hadd2(c1_3, gs11));

                const uint32_t a0 = hfma2(xp0, t0, xp0);
                const uint32_t a1 = hfma2(xp1, t1, xp1);
                const uint32_t a2 = hfma2(xp2, t2, xp2);
                const uint32_t a3 = hfma2(xp3, t3, xp3);

                hmma(acc1[0],  acc1[1],  acc1[2],  acc1[3],  a0,a1,a2,a3, B0.x, B0.y);
                hmma(acc1[4],  acc1[5],  acc1[6],  acc1[7],  a0,a1,a2,a3, B0.z, B0.w);
                hmma(acc1[8],  acc1[9],  acc1[10], acc1[11], a0,a1,a2,a3, B1.x, B1.y);
                hmma(acc1[12], acc1[13], acc1[14], acc1[15], a0,a1,a2,a3, B1.z, B1.w);
                hmma(acc1[16], acc1[17], acc1[18], acc1[19], a0,a1,a2,a3, B2.x, B2.y);
                hmma(acc1[20], acc1[21], acc1[22], acc1[23], a0,a1,a2,a3, B2.z, B2.w);
                hmma(acc1[24], acc1[25], acc1[26], acc1[27], a0,a1,a2,a3, B3.x, B3.y);
                hmma(acc1[28], acc1[29], acc1[30], acc1[31], a0,a1,a2,a3, B3.z, B3.w);
            }
        }
        __syncthreads();   // all done reading bs before restaging
    }

    // ---- epilogue: both tiles ----
    float* ob0 = out + ((size_t)b*Och)*HW + (size_t)h0*Wwi;
    #pragma unroll
    for (int nt = 0; nt < 8; ++nt) {
        const int o0 = nt*8 + qp;
        float* p = ob0 + (size_t)o0*HW;
        p[r0]      = acc0[nt*4 + 0];
        p[HW + r0] = acc0[nt*4 + 1];
        p[r1]      = acc0[nt*4 + 2];
        p[HW + r1] = acc0[nt*4 + 3];
        float* q = p + Wwi;   // row h0+1
        q[r0]      = acc1[nt*4 + 0];
        q[HW + r0] = acc1[nt*4 + 1];
        q[r1]      = acc1[nt*4 + 2];
        q[HW + r1] = acc1[nt*4 + 3];
    }
}

extern "C" void kernel_launch(void* const* d_in, const int* in_sizes, int n_in,
                              void* d_out, int out_size) {
    const float* x  = (const float*)d_in[0];
    const float* gc = (const float*)d_in[1];
    const float* gs = (const float*)d_in[2];
    const float* w  = (const float*)d_in[3];
    float* out = (float*)d_out;

    prep_bfrag<<<(NSTEPS*4*32 + 255)/256, 256>>>(w);

    const int smem_bytes = SMEM_U * 4;
    (void)cudaFuncSetAttribute(paka_hmma,
                               cudaFuncAttributeMaxDynamicSharedMemorySize,
                               smem_bytes);
    paka_hmma<<<NBLK, THREADS, smem_bytes>>>(x, gc, gs, out);
}